// round 4
// baseline (speedup 1.0000x reference)
#include <cuda_runtime.h>

typedef unsigned long long ull;

#define NB 512
#define NS 1024
#define NL 64
#define NC 66
#define LN2 0.6931471805599453f

static __device__ __forceinline__ ull fma2_(ull a, ull b, ull c) {
    ull d; asm("fma.rn.f32x2 %0, %1, %2, %3;" : "=l"(d) : "l"(a), "l"(b), "l"(c)); return d;
}
static __device__ __forceinline__ ull add2_(ull a, ull b) {
    ull d; asm("add.rn.f32x2 %0, %1, %2;" : "=l"(d) : "l"(a), "l"(b)); return d;
}
static __device__ __forceinline__ ull pack2_(float lo, float hi) {
    ull d; asm("mov.b64 %0, {%1, %2};" : "=l"(d) : "f"(lo), "f"(hi)); return d;
}
static __device__ __forceinline__ float2 unpack2_(ull v) {
    float lo, hi; asm("mov.b64 {%0, %1}, %2;" : "=f"(lo), "=f"(hi) : "l"(v)); return make_float2(lo, hi);
}

__global__ void zero_out_kernel(float* out) { out[0] = 0.0f; }

__global__ void __launch_bounds__(64)
crf_fwd_kernel(const float* __restrict__ pred,
               const int*   __restrict__ ref,
               const int*   __restrict__ seq_len,
               const float* __restrict__ trans,
               float*       __restrict__ out)
{
    // one chain per CTA: double-buffered q exchange (64 floats each)
    __shared__ __align__(16) float qbuf[2][64];
    __shared__ float red[2][2];

    const int j = threadIdx.x;           // state 0..63 (one state per thread)
    const int b = blockIdx.x;            // batch 0..511
    const int L = seq_len[b];

    // E column for state j, packed f32x2 over input-state pairs: 32 regs
    ull e2[32];
#pragma unroll
    for (int k = 0; k < 32; ++k)
        e2[k] = pack2_(__expf(trans[(2 * k) * NC + j]), __expf(trans[(2 * k + 1) * NC + j]));
    const float Te = __expf(trans[j * NC + 65]);

    const float* pb = pred + (size_t)b * NS * NL;

    // init: q1 = exp(pred[0] + T[start])
    float q = __expf(pb[j] + trans[64 * NC + j]);
    qbuf[0][j] = q;
    int esum = 0;

    // pred row pipeline: at top of step t, w = exp(row[t-1] - 4)
    const int last = L - 1;
    float r1 = pb[(size_t)min(1, last) * NL + j];
    float r2 = pb[(size_t)min(2, last) * NL + j];
    float w = __expf(r1 - 4.0f);
    r1 = r2;
    r2 = pb[(size_t)min(3, last) * NL + j];

    __syncthreads();

    for (int t = 2; t <= L; ++t) {
        const float* rp = qbuf[t & 1];          // q_{t-1}
        float*       wp = qbuf[(t & 1) ^ 1];
        const ulonglong2* rp2 = (const ulonglong2*)rp;

        // d_j = sum_i q_{t-1}[i] * E[i][j]  : 8 LDS.128 + 32 FFMA2, 4 chains of depth 8
        ull a0 = 0, a1 = 0, a2 = 0, a3 = 0;
#pragma unroll
        for (int k = 0; k < 8; ++k) {
            ulonglong2 v0 = rp2[2 * k];
            ulonglong2 v1 = rp2[2 * k + 1];
            a0 = fma2_(v0.x, e2[4 * k + 0], a0);
            a1 = fma2_(v0.y, e2[4 * k + 1], a1);
            a2 = fma2_(v1.x, e2[4 * k + 2], a2);
            a3 = fma2_(v1.y, e2[4 * k + 3], a3);
        }
        float2 f = unpack2_(add2_(add2_(a0, a1), add2_(a2, a3)));
        float d = (f.x + f.y) * w;

        // O(1) renorm every 8 steps (exact power of 2, uniform across CTA)
        if ((t & 7) == 0) {
            float m = rp[0];
            int e = ((__float_as_int(m) >> 23) & 0xFF) - 127;
            e = max(-100, min(100, e));
            d *= __int_as_float((unsigned)(127 - e) << 23);   // 2^-e
            esum += e;
        }

        q = d;
        wp[j] = d;

        // off-critical-path: next weight + pipeline rotate + prefetch
        w = __expf(r1 - 4.0f);
        r1 = r2;
        r2 = pb[(size_t)min(t + 2, last) * NL + j];
        asm volatile("prefetch.global.L2 [%0];" :: "l"(pb + (size_t)min(t + 8, last) * NL + j));

        __syncthreads();   // nw=2 -> ~7 cyc floor
    }

    // forward terminal (loop ran exactly to L; q holds q_L with esum scalings)
    float v = q * Te;

    // ---- real path score (thread-strided gather) ----
    float rsum = 0.0f;
    const int* rb = ref + (size_t)b * NS;
    for (int t = j; t < L; t += 64) {
        int r = rb[t];
        int p = (t == 0) ? 64 : rb[t - 1];
        rsum += pb[(size_t)t * NL + r] + trans[p * NC + r];
    }
    if (j == 0) rsum += trans[rb[L - 1] * NC + 65];

    // ---- reduce over 64 threads; one atomic per chain ----
#pragma unroll
    for (int o = 16; o; o >>= 1) {
        v    += __shfl_xor_sync(0xFFFFFFFFu, v, o);
        rsum += __shfl_xor_sync(0xFFFFFFFFu, rsum, o);
    }
    const int wi = j >> 5;
    if ((j & 31) == 0) { red[wi][0] = v; red[wi][1] = rsum; }
    __syncthreads();
    if (j == 0) {
        float s  = red[0][0] + red[1][0];
        float rs = red[0][1] + red[1][1];
        float contrib = 4.0f * (float)(L - 1) + LN2 * (float)esum + __logf(s) - rs;
        atomicAdd(out, contrib);
    }
}

extern "C" void kernel_launch(void* const* d_in, const int* in_sizes, int n_in,
                              void* d_out, int out_size)
{
    const float* pred  = (const float*)d_in[0];
    const int*   refp  = (const int*)d_in[1];
    const int*   seq   = (const int*)d_in[2];
    const float* trans = (const float*)d_in[3];
    float* outp = (float*)d_out;

    zero_out_kernel<<<1, 1>>>(outp);
    crf_fwd_kernel<<<NB, 64>>>(pred, refp, seq, trans, outp);
}

// round 5
// speedup vs baseline: 1.2125x; 1.2125x over previous
#include <cuda_runtime.h>

typedef unsigned long long ull;

#define NB 512
#define NS 1024
#define NL 64
#define NC 66
#define LN2 0.6931471805599453f

static __device__ __forceinline__ ull fma2_(ull a, ull b, ull c) {
    ull d; asm("fma.rn.f32x2 %0, %1, %2, %3;" : "=l"(d) : "l"(a), "l"(b), "l"(c)); return d;
}
static __device__ __forceinline__ ull add2_(ull a, ull b) {
    ull d; asm("add.rn.f32x2 %0, %1, %2;" : "=l"(d) : "l"(a), "l"(b)); return d;
}
static __device__ __forceinline__ ull pack2_(float lo, float hi) {
    ull d; asm("mov.b64 %0, {%1, %2};" : "=l"(d) : "f"(lo), "f"(hi)); return d;
}
static __device__ __forceinline__ float2 unpack2_(ull v) {
    float lo, hi; asm("mov.b64 {%0, %1}, %2;" : "=f"(lo), "=f"(hi) : "l"(v)); return make_float2(lo, hi);
}

__global__ void zero_out_kernel(float* out) { out[0] = 0.0f; }

__global__ void __launch_bounds__(128, 1)
crf_fwd_kernel(const float* __restrict__ pred,
               const int*   __restrict__ ref,
               const int*   __restrict__ seq_len,
               const float* __restrict__ trans,
               float*       __restrict__ out)
{
    // per-warp q double buffer: 4 warps x 2 bufs x 64 floats
    __shared__ __align__(16) float qbuf[4][2][64];

    const int w = threadIdx.x >> 5;        // warp in CTA: one chain each
    const int l = threadIdx.x & 31;        // lane
    const int b = (blockIdx.x << 2) + w;   // batch 0..511
    const int j0 = 2 * l, j1 = 2 * l + 1;  // the two states this thread owns
    const int L = seq_len[b];

    // E columns for states j0, j1 (packed f32x2 over input-state pairs): 128 regs
    ull e0[32], e1[32];
#pragma unroll
    for (int k = 0; k < 32; ++k) {
        e0[k] = pack2_(__expf(trans[(2 * k) * NC + j0]), __expf(trans[(2 * k + 1) * NC + j0]));
        e1[k] = pack2_(__expf(trans[(2 * k) * NC + j1]), __expf(trans[(2 * k + 1) * NC + j1]));
    }
    const float Te0 = __expf(trans[j0 * NC + 65]);
    const float Te1 = __expf(trans[j1 * NC + 65]);

    const float* pb = pred + (size_t)b * NS * NL;

    // init: q1 = exp(pred[0] + T[start])
    float q0 = __expf(pb[j0] + trans[64 * NC + j0]);
    float q1 = __expf(pb[j1] + trans[64 * NC + j1]);

    float v = q0 * Te0 + q1 * Te1;   // covers L == 1
    int ecap = 0, esum = 0;

    float* buf0 = qbuf[w][0];
    float* buf1 = qbuf[w][1];
    ((float2*)buf0)[l] = make_float2(q0, q1);   // q_1 in buf0

    // pred row pipeline: at top of step t, (w0,w1) = exp(row[t-1] - 4)
    const int last = L - 1;
    float2 r1 = ((const float2*)(pb + (size_t)min(1, last) * NL))[l];
    float2 r2 = ((const float2*)(pb + (size_t)min(2, last) * NL))[l];
    float w0 = __expf(r1.x - 4.0f);
    float w1 = __expf(r1.y - 4.0f);
    r1 = r2;
    r2 = ((const float2*)(pb + (size_t)min(3, last) * NL))[l];

    __syncwarp(0xFFFFFFFFu);

    for (int t = 2; t <= L; ++t) {
        const float* rp = (t & 1) ? buf1 : buf0;
        float*       wp = (t & 1) ? buf0 : buf1;
        const ulonglong2* rp2 = (const ulonglong2*)rp;

        // -------- phase 1: batch ALL q loads (16 independent LDS.128) --------
        ulonglong2 qv[16];
#pragma unroll
        for (int k = 0; k < 16; ++k) qv[k] = rp2[k];

        // -------- phase 2: dual matvec, 8 accumulators (dep depth 8) --------
        ull a0 = 0, a1 = 0, a2 = 0, a3 = 0;   // output j0
        ull c0 = 0, c1 = 0, c2 = 0, c3 = 0;   // output j1
#pragma unroll
        for (int k = 0; k < 4; ++k) {
            a0 = fma2_(qv[4 * k + 0].x, e0[8 * k + 0], a0);
            c0 = fma2_(qv[4 * k + 0].x, e1[8 * k + 0], c0);
            a1 = fma2_(qv[4 * k + 0].y, e0[8 * k + 1], a1);
            c1 = fma2_(qv[4 * k + 0].y, e1[8 * k + 1], c1);
            a2 = fma2_(qv[4 * k + 1].x, e0[8 * k + 2], a2);
            c2 = fma2_(qv[4 * k + 1].x, e1[8 * k + 2], c2);
            a3 = fma2_(qv[4 * k + 1].y, e0[8 * k + 3], a3);
            c3 = fma2_(qv[4 * k + 1].y, e1[8 * k + 3], c3);
            a0 = fma2_(qv[4 * k + 2].x, e0[8 * k + 4], a0);
            c0 = fma2_(qv[4 * k + 2].x, e1[8 * k + 4], c0);
            a1 = fma2_(qv[4 * k + 2].y, e0[8 * k + 5], a1);
            c1 = fma2_(qv[4 * k + 2].y, e1[8 * k + 5], c1);
            a2 = fma2_(qv[4 * k + 3].x, e0[8 * k + 6], a2);
            c2 = fma2_(qv[4 * k + 3].x, e1[8 * k + 6], c2);
            a3 = fma2_(qv[4 * k + 3].y, e0[8 * k + 7], a3);
            c3 = fma2_(qv[4 * k + 3].y, e1[8 * k + 7], c3);
        }
        float2 fa = unpack2_(add2_(add2_(a0, a1), add2_(a2, a3)));
        float2 fc = unpack2_(add2_(add2_(c0, c1), add2_(c2, c3)));
        float d0 = (fa.x + fa.y) * w0;
        float d1 = (fc.x + fc.y) * w1;

        // O(1) renorm every 8 steps (exact power of 2, uniform across warp)
        if ((t & 7) == 0) {
            float m = rp[0];
            int e = ((__float_as_int(m) >> 23) & 0xFF) - 127;
            e = max(-100, min(100, e));
            float f = __int_as_float((unsigned)(127 - e) << 23);  // 2^-e
            d0 *= f; d1 *= f;
            esum += e;
        }

        if (t == L) { v = d0 * Te0 + d1 * Te1; ecap = esum; }

        ((float2*)wp)[l] = make_float2(d0, d1);

        // off-critical-path: next weight + pipeline rotate + prefetch
        w0 = __expf(r1.x - 4.0f);
        w1 = __expf(r1.y - 4.0f);
        r1 = r2;
        r2 = ((const float2*)(pb + (size_t)min(t + 2, last) * NL))[l];
        asm volatile("prefetch.global.L2 [%0];" :: "l"(pb + (size_t)min(t + 6, last) * NL + j0));

        __syncwarp(0xFFFFFFFFu);
    }

    // ---- real path score (lane-strided gather) ----
    float rsum = 0.0f;
    const int* rb = ref + (size_t)b * NS;
    for (int t = l; t < L; t += 32) {
        int r = rb[t];
        int p = (t == 0) ? 64 : rb[t - 1];
        rsum += pb[(size_t)t * NL + r] + trans[p * NC + r];
    }
    if (l == 0) rsum += trans[rb[L - 1] * NC + 65];

    // ---- in-warp reduction; one atomic per chain ----
#pragma unroll
    for (int o = 16; o; o >>= 1) {
        v    += __shfl_xor_sync(0xFFFFFFFFu, v, o);
        rsum += __shfl_xor_sync(0xFFFFFFFFu, rsum, o);
    }
    if (l == 0) {
        float contrib = 4.0f * (float)(L - 1) + LN2 * (float)ecap + __logf(v) - rsum;
        atomicAdd(out, contrib);
    }
}

extern "C" void kernel_launch(void* const* d_in, const int* in_sizes, int n_in,
                              void* d_out, int out_size)
{
    const float* pred  = (const float*)d_in[0];
    const int*   refp  = (const int*)d_in[1];
    const int*   seq   = (const int*)d_in[2];
    const float* trans = (const float*)d_in[3];
    float* outp = (float*)d_out;

    zero_out_kernel<<<1, 1>>>(outp);
    crf_fwd_kernel<<<NB / 4, 128>>>(pred, refp, seq, trans, outp);
}